// round 9
// baseline (speedup 1.0000x reference)
#include <cuda_runtime.h>
#include <cuda_fp16.h>
#include <cstdint>
#include <cstddef>

#define DINL __device__ __forceinline__

static constexpr int BATCH = 64;
static constexpr int SEQ   = 512;
static constexpr int EMB   = 512;
static constexpr int HID   = 512;
static constexpr int G4    = 2048;
static constexpr int NTOK  = BATCH * SEQ;

// Permuted fp16 weights: 0=Wf,1=Wb,2=Uf,3=Ub.
// Row r: rblk=r>>5, lr=r&31, g=lr>>3, jp=lr&7  <->  original column g*512 + rblk*8 + jp
__device__ __align__(16) __half g_APERM[4][G4][EMB];
__device__ __align__(16) __half g_X[(size_t)NTOK * EMB];
__device__ __align__(16) __half g_XW[2][G4][NTOK];
__device__ __align__(16) __half g_H[2][2][BATCH * HID];
__device__ float g_BIAS[2][G4];
__device__ unsigned g_bar[128];   // per-dir counters at [0] and [64]

// ---------------- helpers ----------------
DINL void ldsm_x4(uint32_t& r0, uint32_t& r1, uint32_t& r2, uint32_t& r3, uint32_t addr) {
    asm volatile("ldmatrix.sync.aligned.m8n8.x4.shared.b16 {%0,%1,%2,%3}, [%4];"
                 : "=r"(r0), "=r"(r1), "=r"(r2), "=r"(r3) : "r"(addr));
}
DINL void mma16816(float* d, uint32_t a0, uint32_t a1, uint32_t a2, uint32_t a3,
                   uint32_t b0, uint32_t b1) {
    asm volatile("mma.sync.aligned.m16n8k16.row.col.f32.f16.f16.f32 "
                 "{%0,%1,%2,%3}, {%4,%5,%6,%7}, {%8,%9}, {%0,%1,%2,%3};"
                 : "+f"(d[0]), "+f"(d[1]), "+f"(d[2]), "+f"(d[3])
                 : "r"(a0), "r"(a1), "r"(a2), "r"(a3), "r"(b0), "r"(b1));
}
DINL float sigf(float x) { return 1.0f / (1.0f + __expf(-x)); }
DINL uint32_t pack_h2(float a, float b) {
    return ((uint32_t)__half_as_ushort(__float2half_rn(b)) << 16) |
           (uint32_t)__half_as_ushort(__float2half_rn(a));
}
DINL uint4 ldg_cg(const void* p) {
    uint4 v;
    asm volatile("ld.global.cg.v4.u32 {%0,%1,%2,%3}, [%4];"
                 : "=r"(v.x), "=r"(v.y), "=r"(v.z), "=r"(v.w) : "l"(p));
    return v;
}
DINL void stg_cg32(void* p, uint32_t v) {
    asm volatile("st.global.cg.u32 [%0], %1;" :: "l"(p), "r"(v) : "memory");
}
DINL void cp16(uint32_t dst, const void* src) {
    asm volatile("cp.async.cg.shared.global [%0], [%1], 16;" :: "r"(dst), "l"(src) : "memory");
}
#define CP_COMMIT() asm volatile("cp.async.commit_group;" ::: "memory")
#define CP_WAIT(N)  asm volatile("cp.async.wait_group %0;" :: "n"(N) : "memory")

// ---------------- phase kernels ----------------
__global__ void init_kernel() {
    unsigned idx = blockIdx.x * blockDim.x + threadIdx.x;
    reinterpret_cast<uint32_t*>(g_H)[idx] = 0u;   // zero parity-0 h, both dirs
    if (idx < 128) g_bar[idx] = 0u;
}

// Coalesced transpose into permuted layout (R6 mapping: 8-unit blocks).
__global__ void __launch_bounds__(256) prep_w_kernel(
        const float* __restrict__ Wf, const float* __restrict__ Uf,
        const float* __restrict__ bf, const float* __restrict__ Wb,
        const float* __restrict__ Ub, const float* __restrict__ bb) {
    __shared__ __half tile[32][520];
    int m = blockIdx.x >> 6;
    int blk = blockIdx.x & 63;          // == rblk (32-row block == r>>5)
    int rbase = blk * 32;
    int tid = threadIdx.x;
    int lr = tid & 31, eo = tid >> 5;
    int g = lr >> 3, jp = lr & 7;
    int col = g * 512 + blk * 8 + jp;
    const float* src = (m == 0) ? Wf : (m == 1) ? Wb : (m == 2) ? Uf : Ub;
#pragma unroll 8
    for (int es = 0; es < 64; es++) {
        int e = es * 8 + eo;
        tile[lr][e] = __float2half(src[(size_t)e * G4 + col]);
    }
    if (m < 2 && tid < 32) g_BIAS[m][rbase + lr] = (m ? bb : bf)[col];
    __syncthreads();
    int row = tid >> 3, c = tid & 7;
#pragma unroll
    for (int q = 0; q < 8; q++)
        *(uint4*)&g_APERM[m][rbase + row][(c + q * 8) * 8] =
            *(uint4*)&tile[row][(c + q * 8) * 8];
}

__global__ void gather_x_kernel(const int* __restrict__ tokens, const float* __restrict__ emb) {
    int i = blockIdx.x;
    int s = i >> 6, b = i & 63;
    int tok = tokens[b * SEQ + s];
    float4 v = reinterpret_cast<const float4*>(emb + (size_t)tok * EMB)[threadIdx.x];
    __half2* dst = reinterpret_cast<__half2*>(g_X + (size_t)i * EMB);
    dst[threadIdx.x * 2]     = __floats2half2_rn(v.x, v.y);
    dst[threadIdx.x * 2 + 1] = __floats2half2_rn(v.z, v.w);
}

// ---------------- xW GEMM (HMMA + cp.async double buffer; best known) ----------------
static constexpr int XBUF = 10240;
static constexpr int XW_SMEM = 4 * XBUF;

__global__ void __launch_bounds__(256) xw_gemm_kernel() {
    extern __shared__ char smx[];
    uint32_t sa = (uint32_t)__cvta_generic_to_shared(smx);
    uint32_t sbv = sa + 2 * XBUF;
    int dir = blockIdx.z, rbase = blockIdx.y * 128, ibase = blockIdx.x * 128;
    int tid = threadIdx.x, w = tid >> 5, lane = tid & 31;
    int wm = w & 3, wn = w >> 2;
    float acc[2][8][4];
#pragma unroll
    for (int a = 0; a < 2; a++)
#pragma unroll
        for (int b = 0; b < 8; b++)
#pragma unroll
            for (int c = 0; c < 4; c++) acc[a][b][c] = 0.0f;
    const __half* gA = &g_APERM[dir][0][0];

    auto load_chunk = [&](int kc, int buf) {
#pragma unroll
        for (int p = 0; p < 2; p++) {
            int ch = tid + p * 256, row = ch >> 2, c = ch & 3;
            cp16(sa  + buf * XBUF + (uint32_t)(row * 40 + c * 8) * 2,
                 &gA[(size_t)(rbase + row) * EMB + kc * 32 + c * 8]);
            cp16(sbv + buf * XBUF + (uint32_t)(row * 40 + c * 8) * 2,
                 &g_X[(size_t)(ibase + row) * EMB + kc * 32 + c * 8]);
        }
        CP_COMMIT();
    };

    load_chunk(0, 0);
    for (int kc = 0; kc < 16; kc++) {
        int cur = kc & 1;
        if (kc < 15) { load_chunk(kc + 1, cur ^ 1); CP_WAIT(1); }
        else         { CP_WAIT(0); }
        __syncthreads();
        uint32_t as_base = sa  + cur * XBUF;
        uint32_t bs_base = sbv + cur * XBUF;
#pragma unroll
        for (int kk = 0; kk < 2; kk++) {
            uint32_t a[2][4];
#pragma unroll
            for (int mt = 0; mt < 2; mt++) {
                int rr = wm * 32 + mt * 16 + (lane & 15);
                int cc = kk * 16 + ((lane >> 4) & 1) * 8;
                ldsm_x4(a[mt][0], a[mt][1], a[mt][2], a[mt][3],
                        as_base + (uint32_t)(rr * 40 + cc) * 2);
            }
            uint32_t bq[8][2];
#pragma unroll
            for (int bp = 0; bp < 4; bp++) {
                int rr = wn * 64 + bp * 16 + ((lane >> 4) << 3) + (lane & 7);
                int cc = kk * 16 + ((lane >> 3) & 1) * 8;
                ldsm_x4(bq[bp * 2][0], bq[bp * 2][1], bq[bp * 2 + 1][0], bq[bp * 2 + 1][1],
                        bs_base + (uint32_t)(rr * 40 + cc) * 2);
            }
#pragma unroll
            for (int mt = 0; mt < 2; mt++)
#pragma unroll
                for (int nt = 0; nt < 8; nt++)
                    mma16816(acc[mt][nt], a[mt][0], a[mt][1], a[mt][2], a[mt][3],
                             bq[nt][0], bq[nt][1]);
        }
        __syncthreads();
    }
    __half* gxw = &g_XW[dir][0][0];
#pragma unroll
    for (int mt = 0; mt < 2; mt++)
#pragma unroll
        for (int nt = 0; nt < 8; nt++) {
            size_t row = rbase + wm * 32 + mt * 16 + (lane >> 2);
            int col = ibase + wn * 64 + nt * 8 + (lane & 3) * 2;
            *(__half2*)&gxw[row * NTOK + col]       = __floats2half2_rn(acc[mt][nt][0], acc[mt][nt][1]);
            *(__half2*)&gxw[(row + 8) * NTOK + col] = __floats2half2_rn(acc[mt][nt][2], acc[mt][nt][3]);
        }
}

// ---------------- persistent recurrence (R6 shape + latency overlap) ----------------
// 128 CTAs = 2 dirs x 64 blocks of 32 gate rows (4 gates x 8 hidden units).
// Warps: mt = w>>2 (m16 tile of 2), nq = w&3 (batch quarter, n16).
static constexpr int HS_STRIDE = 520;   // halves
static constexpr int XS_STRIDE = 72;    // halves
static constexpr int ZS_STRIDE = 68;    // floats
static constexpr int SO_H  = 0;                        // 64 x 520 x 2 = 66560
static constexpr int SO_XW = 66560;                    // 32 x 72 x 2  = 4608
static constexpr int SO_Z  = 71168;                    // 32 x 68 x 4  = 8704
static constexpr int SO_B  = 79872;                    // 32 x 4
static constexpr int SMEM_SZ = 80000;

__global__ void __launch_bounds__(256, 1) recur_kernel(float* __restrict__ out) {
    extern __shared__ char smem[];
    __half* hs = (__half*)(smem + SO_H);
    __half* xs = (__half*)(smem + SO_XW);
    float*  zs = (float*)(smem + SO_Z);
    float*  bsm = (float*)(smem + SO_B);

    int cta = blockIdx.x;
    int dir = cta >> 6, rblk = cta & 63;
    int rbase = rblk * 32;
    int tid = threadIdx.x, w = tid >> 5, lane = tid & 31;
    int mt = w >> 2, nq = w & 3;
    uint32_t hs_base = (uint32_t)__cvta_generic_to_shared(hs);
    unsigned* bar = &g_bar[dir * 64];

    // ---- stage U (32 rows x 512), ldsm A-fragments into registers ----
#pragma unroll
    for (int p = 0; p < 8; p++) {
        int idx = tid + p * 256;
        int row = idx >> 6, c = idx & 63;
        *(uint4*)&hs[row * HS_STRIDE + c * 8] =
            *(const uint4*)&g_APERM[2 + dir][rbase + row][c * 8];
    }
    if (tid < 32) bsm[tid] = g_BIAS[dir][rbase + tid];
    __syncthreads();

    uint32_t a[32][4];
#pragma unroll
    for (int kk = 0; kk < 32; kk++) {
        int rr = mt * 16 + (lane & 15);
        int cc = kk * 16 + ((lane >> 4) & 1) * 8;
        ldsm_x4(a[kk][0], a[kk][1], a[kk][2], a[kk][3],
                hs_base + (uint32_t)(rr * HS_STRIDE + cc) * 2);
    }
    __syncthreads();

    float creg[2] = {0.f, 0.f};
    int eb = tid & 63;          // batch
    int hq = tid >> 6;          // hidden pair index (0..3), jp = hq*2 + q
    int xw_row = tid >> 3, xw_c = tid & 7;

    // prefetch XW for t = 0
    int sx0 = dir ? (SEQ - 1) : 0;
    uint4 xwr = *(const uint4*)&g_XW[dir][rbase + xw_row][sx0 * 64 + xw_c * 8];

    for (int t = 0; t < SEQ; t++) {
        int par = t & 1;
        int sx = dir ? (SEQ - 1 - t) : t;
        const __half* hsrc = &g_H[par][dir][0];

        // STS prefetched XW tile
        *(uint4*)&xs[xw_row * XS_STRIDE + xw_c * 8] = xwr;

        // issue ALL h loads (high MLP): half1 = cols 0..255, half2 = cols 256..511
        uint4 h1[8], h2[8];
#pragma unroll
        for (int p = 0; p < 8; p++) {
            int idx = tid + p * 256;            // 2048 uint4
            int row = idx >> 5, c = idx & 31;
            h1[p] = ldg_cg(&hsrc[row * HID + c * 8]);
        }
#pragma unroll
        for (int p = 0; p < 8; p++) {
            int idx = tid + p * 256;
            int row = idx >> 5, c = 32 + (idx & 31);
            h2[p] = ldg_cg(&hsrc[row * HID + c * 8]);
        }
        // STS half1, sync, MMA first half while half2 LDGs complete
#pragma unroll
        for (int p = 0; p < 8; p++) {
            int idx = tid + p * 256;
            int row = idx >> 5, c = idx & 31;
            *(uint4*)&hs[row * HS_STRIDE + c * 8] = h1[p];
        }
        __syncthreads();

        float acc[2][4];
#pragma unroll
        for (int i = 0; i < 2; i++)
#pragma unroll
            for (int c = 0; c < 4; c++) acc[i][c] = 0.0f;

#pragma unroll
        for (int kk = 0; kk < 16; kk++) {
            uint32_t b0, b1, b2, b3;
            int rr = nq * 16 + ((lane >> 4) << 3) + (lane & 7);
            int cc = kk * 16 + ((lane >> 3) & 1) * 8;
            ldsm_x4(b0, b1, b2, b3, hs_base + (uint32_t)(rr * HS_STRIDE + cc) * 2);
            mma16816(acc[0], a[kk][0], a[kk][1], a[kk][2], a[kk][3], b0, b1);
            mma16816(acc[1], a[kk][0], a[kk][1], a[kk][2], a[kk][3], b2, b3);
        }
        __syncthreads();            // everyone done reading half1 region? (no: half2 is disjoint) — orders STS half2 vs MMA half1 reads below
#pragma unroll
        for (int p = 0; p < 8; p++) {
            int idx = tid + p * 256;
            int row = idx >> 5, c = 32 + (idx & 31);
            *(uint4*)&hs[row * HS_STRIDE + c * 8] = h2[p];
        }
        __syncthreads();
#pragma unroll
        for (int kk = 16; kk < 32; kk++) {
            uint32_t b0, b1, b2, b3;
            int rr = nq * 16 + ((lane >> 4) << 3) + (lane & 7);
            int cc = kk * 16 + ((lane >> 3) & 1) * 8;
            ldsm_x4(b0, b1, b2, b3, hs_base + (uint32_t)(rr * HS_STRIDE + cc) * 2);
            mma16816(acc[0], a[kk][0], a[kk][1], a[kk][2], a[kk][3], b0, b1);
            mma16816(acc[1], a[kk][0], a[kk][1], a[kk][2], a[kk][3], b2, b3);
        }
        // z -> SMEM exchange
#pragma unroll
        for (int i = 0; i < 2; i++) {
            int row = mt * 16 + (lane >> 2);
            int col = nq * 16 + i * 8 + (lane & 3) * 2;
            *(float2*)&zs[row * ZS_STRIDE + col]       = make_float2(acc[i][0], acc[i][1]);
            *(float2*)&zs[(row + 8) * ZS_STRIDE + col] = make_float2(acc[i][2], acc[i][3]);
        }
        __syncthreads();

        // cell update: thread owns (batch eb, hidden units hq*2, hq*2+1)
        float hv[2];
#pragma unroll
        for (int q = 0; q < 2; q++) {
            int jp = hq * 2 + q;
            float z0 = zs[jp * ZS_STRIDE + eb]        + __half2float(xs[jp * XS_STRIDE + eb])        + bsm[jp];
            float z1 = zs[(8 + jp) * ZS_STRIDE + eb]  + __half2float(xs[(8 + jp) * XS_STRIDE + eb])  + bsm[8 + jp];
            float z2 = zs[(16 + jp) * ZS_STRIDE + eb] + __half2float(xs[(16 + jp) * XS_STRIDE + eb]) + bsm[16 + jp];
            float z3 = zs[(24 + jp) * ZS_STRIDE + eb] + __half2float(xs[(24 + jp) * XS_STRIDE + eb]) + bsm[24 + jp];
            float ig = sigf(z0), fg = sigf(z1), gg = tanhf(z2), og = sigf(z3);
            creg[q] = fg * creg[q] + ig * gg;
            hv[q] = og * tanhf(creg[q]);
        }
        stg_cg32(&g_H[par ^ 1][dir][eb * HID + rblk * 8 + hq * 2], pack_h2(hv[0], hv[1]));
        *(float2*)&out[((size_t)eb * SEQ + sx) * 1024 + dir * 512 + rblk * 8 + hq * 2] =
            make_float2(hv[0], hv[1]);

        // per-direction grid barrier (64 CTAs each); XW[t+1] prefetch hides in the spin
        __syncthreads();
        if (tid == 0) {
            asm volatile("red.release.gpu.global.add.u32 [%0], %1;" :: "l"(bar), "r"(1u) : "memory");
        }
        if (t + 1 < SEQ) {
            int sxn = dir ? (SEQ - 2 - t) : (t + 1);
            xwr = *(const uint4*)&g_XW[dir][rbase + xw_row][sxn * 64 + xw_c * 8];
        }
        if (tid == 0) {
            unsigned tgt = 64u * (unsigned)(t + 1), v;
            do {
                asm volatile("ld.acquire.gpu.global.u32 %0, [%1];" : "=r"(v) : "l"(bar));
            } while (v < tgt);
        }
        __syncthreads();
    }
}

// ---------------- launch ----------------
extern "C" void kernel_launch(void* const* d_in, const int* in_sizes, int n_in,
                              void* d_out, int out_size) {
    const int*   tokens = (const int*)d_in[0];
    const float* emb    = (const float*)d_in[1];
    const float* Wf     = (const float*)d_in[2];
    const float* Uf     = (const float*)d_in[3];
    const float* bf     = (const float*)d_in[4];
    const float* Wb     = (const float*)d_in[5];
    const float* Ub     = (const float*)d_in[6];
    const float* bb     = (const float*)d_in[7];
    float* out = (float*)d_out;

    cudaFuncSetAttribute(recur_kernel, cudaFuncAttributeMaxDynamicSharedMemorySize, SMEM_SZ);
    cudaFuncSetAttribute(xw_gemm_kernel, cudaFuncAttributeMaxDynamicSharedMemorySize, XW_SMEM);

    init_kernel<<<128, 256>>>();
    prep_w_kernel<<<256, 256>>>(Wf, Uf, bf, Wb, Ub, bb);
    gather_x_kernel<<<NTOK, 128>>>(tokens, emb);
    dim3 gg(256, 16, 2);
    xw_gemm_kernel<<<gg, 256, XW_SMEM>>>();
    recur_kernel<<<128, 256, SMEM_SZ>>>(out);
}

// round 10
// speedup vs baseline: 1.4626x; 1.4626x over previous
#include <cuda_runtime.h>
#include <cuda_fp16.h>
#include <cstdint>
#include <cstddef>

#define DINL __device__ __forceinline__

static constexpr int BATCH = 64;
static constexpr int SEQ   = 512;
static constexpr int EMB   = 512;
static constexpr int HID   = 512;
static constexpr int G4    = 2048;
static constexpr int NTOK  = BATCH * SEQ;

// Permuted fp16 weights: 0=Wf,1=Wb,2=Uf,3=Ub.
// Row r: rblk=r>>5, lr=r&31, g=lr>>3, jp=lr&7  <->  original column g*512 + rblk*8 + jp
__device__ __align__(16) __half g_APERM[4][G4][EMB];
__device__ __align__(16) __half g_X[(size_t)NTOK * EMB];
__device__ __align__(16) __half g_XW[2][G4][NTOK];
__device__ __align__(16) __half g_H[2][2][BATCH * HID];
__device__ float g_BIAS[2][G4];
__device__ unsigned g_bar[128];   // per-dir counters at [0] and [64]

// ---------------- helpers ----------------
DINL void ldsm_x4(uint32_t& r0, uint32_t& r1, uint32_t& r2, uint32_t& r3, uint32_t addr) {
    asm volatile("ldmatrix.sync.aligned.m8n8.x4.shared.b16 {%0,%1,%2,%3}, [%4];"
                 : "=r"(r0), "=r"(r1), "=r"(r2), "=r"(r3) : "r"(addr));
}
DINL void mma16816(float* d, uint32_t a0, uint32_t a1, uint32_t a2, uint32_t a3,
                   uint32_t b0, uint32_t b1) {
    asm volatile("mma.sync.aligned.m16n8k16.row.col.f32.f16.f16.f32 "
                 "{%0,%1,%2,%3}, {%4,%5,%6,%7}, {%8,%9}, {%0,%1,%2,%3};"
                 : "+f"(d[0]), "+f"(d[1]), "+f"(d[2]), "+f"(d[3])
                 : "r"(a0), "r"(a1), "r"(a2), "r"(a3), "r"(b0), "r"(b1));
}
DINL float sigf(float x) { return 1.0f / (1.0f + __expf(-x)); }
DINL uint32_t pack_h2(float a, float b) {
    return ((uint32_t)__half_as_ushort(__float2half_rn(b)) << 16) |
           (uint32_t)__half_as_ushort(__float2half_rn(a));
}
DINL uint4 ldg_cg(const void* p) {
    uint4 v;
    asm volatile("ld.global.cg.v4.u32 {%0,%1,%2,%3}, [%4];"
                 : "=r"(v.x), "=r"(v.y), "=r"(v.z), "=r"(v.w) : "l"(p));
    return v;
}
DINL void stg_cg32(void* p, uint32_t v) {
    asm volatile("st.global.cg.u32 [%0], %1;" :: "l"(p), "r"(v) : "memory");
}
DINL void cp16(uint32_t dst, const void* src) {
    asm volatile("cp.async.cg.shared.global [%0], [%1], 16;" :: "r"(dst), "l"(src) : "memory");
}
#define CP_COMMIT() asm volatile("cp.async.commit_group;" ::: "memory")
#define CP_WAIT(N)  asm volatile("cp.async.wait_group %0;" :: "n"(N) : "memory")

// ---------------- phase kernels ----------------
__global__ void init_kernel() {
    unsigned idx = blockIdx.x * blockDim.x + threadIdx.x;
    reinterpret_cast<uint32_t*>(g_H)[idx] = 0u;   // zero parity-0 h, both dirs
    if (idx < 128) g_bar[idx] = 0u;
}

// Coalesced transpose into permuted layout.
__global__ void __launch_bounds__(256) prep_w_kernel(
        const float* __restrict__ Wf, const float* __restrict__ Uf,
        const float* __restrict__ bf, const float* __restrict__ Wb,
        const float* __restrict__ Ub, const float* __restrict__ bb) {
    __shared__ __half tile[32][520];
    int m = blockIdx.x >> 6;
    int blk = blockIdx.x & 63;          // rblk = r>>5
    int rbase = blk * 32;
    int tid = threadIdx.x;
    int lr = tid & 31, eo = tid >> 5;
    int g = lr >> 3, jp = lr & 7;
    int col = g * 512 + blk * 8 + jp;
    const float* src = (m == 0) ? Wf : (m == 1) ? Wb : (m == 2) ? Uf : Ub;
#pragma unroll 8
    for (int es = 0; es < 64; es++) {
        int e = es * 8 + eo;
        tile[lr][e] = __float2half(src[(size_t)e * G4 + col]);
    }
    if (m < 2 && tid < 32) g_BIAS[m][rbase + lr] = (m ? bb : bf)[col];
    __syncthreads();
    int row = tid >> 3, c = tid & 7;
#pragma unroll
    for (int q = 0; q < 8; q++)
        *(uint4*)&g_APERM[m][rbase + row][(c + q * 8) * 8] =
            *(uint4*)&tile[row][(c + q * 8) * 8];
}

__global__ void gather_x_kernel(const int* __restrict__ tokens, const float* __restrict__ emb) {
    int i = blockIdx.x;
    int s = i >> 6, b = i & 63;
    int tok = tokens[b * SEQ + s];
    float4 v = reinterpret_cast<const float4*>(emb + (size_t)tok * EMB)[threadIdx.x];
    __half2* dst = reinterpret_cast<__half2*>(g_X + (size_t)i * EMB);
    dst[threadIdx.x * 2]     = __floats2half2_rn(v.x, v.y);
    dst[threadIdx.x * 2 + 1] = __floats2half2_rn(v.z, v.w);
}

// ---------------- xW GEMM (HMMA + cp.async double buffer) ----------------
static constexpr int XBUF = 10240;
static constexpr int XW_SMEM = 4 * XBUF;

__global__ void __launch_bounds__(256) xw_gemm_kernel() {
    extern __shared__ char smx[];
    uint32_t sa = (uint32_t)__cvta_generic_to_shared(smx);
    uint32_t sbv = sa + 2 * XBUF;
    int dir = blockIdx.z, rbase = blockIdx.y * 128, ibase = blockIdx.x * 128;
    int tid = threadIdx.x, w = tid >> 5, lane = tid & 31;
    int wm = w & 3, wn = w >> 2;
    float acc[2][8][4];
#pragma unroll
    for (int a = 0; a < 2; a++)
#pragma unroll
        for (int b = 0; b < 8; b++)
#pragma unroll
            for (int c = 0; c < 4; c++) acc[a][b][c] = 0.0f;
    const __half* gA = &g_APERM[dir][0][0];

    auto load_chunk = [&](int kc, int buf) {
#pragma unroll
        for (int p = 0; p < 2; p++) {
            int ch = tid + p * 256, row = ch >> 2, c = ch & 3;
            cp16(sa  + buf * XBUF + (uint32_t)(row * 40 + c * 8) * 2,
                 &gA[(size_t)(rbase + row) * EMB + kc * 32 + c * 8]);
            cp16(sbv + buf * XBUF + (uint32_t)(row * 40 + c * 8) * 2,
                 &g_X[(size_t)(ibase + row) * EMB + kc * 32 + c * 8]);
        }
        CP_COMMIT();
    };

    load_chunk(0, 0);
    for (int kc = 0; kc < 16; kc++) {
        int cur = kc & 1;
        if (kc < 15) { load_chunk(kc + 1, cur ^ 1); CP_WAIT(1); }
        else         { CP_WAIT(0); }
        __syncthreads();
        uint32_t as_base = sa  + cur * XBUF;
        uint32_t bs_base = sbv + cur * XBUF;
#pragma unroll
        for (int kk = 0; kk < 2; kk++) {
            uint32_t a[2][4];
#pragma unroll
            for (int mt = 0; mt < 2; mt++) {
                int rr = wm * 32 + mt * 16 + (lane & 15);
                int cc = kk * 16 + ((lane >> 4) & 1) * 8;
                ldsm_x4(a[mt][0], a[mt][1], a[mt][2], a[mt][3],
                        as_base + (uint32_t)(rr * 40 + cc) * 2);
            }
            uint32_t bq[8][2];
#pragma unroll
            for (int bp = 0; bp < 4; bp++) {
                int rr = wn * 64 + bp * 16 + ((lane >> 4) << 3) + (lane & 7);
                int cc = kk * 16 + ((lane >> 3) & 1) * 8;
                ldsm_x4(bq[bp * 2][0], bq[bp * 2][1], bq[bp * 2 + 1][0], bq[bp * 2 + 1][1],
                        bs_base + (uint32_t)(rr * 40 + cc) * 2);
            }
#pragma unroll
            for (int mt = 0; mt < 2; mt++)
#pragma unroll
                for (int nt = 0; nt < 8; nt++)
                    mma16816(acc[mt][nt], a[mt][0], a[mt][1], a[mt][2], a[mt][3],
                             bq[nt][0], bq[nt][1]);
        }
        __syncthreads();
    }
    __half* gxw = &g_XW[dir][0][0];
#pragma unroll
    for (int mt = 0; mt < 2; mt++)
#pragma unroll
        for (int nt = 0; nt < 8; nt++) {
            size_t row = rbase + wm * 32 + mt * 16 + (lane >> 2);
            int col = ibase + wn * 64 + nt * 8 + (lane & 3) * 2;
            *(__half2*)&gxw[row * NTOK + col]       = __floats2half2_rn(acc[mt][nt][0], acc[mt][nt][1]);
            *(__half2*)&gxw[(row + 8) * NTOK + col] = __floats2half2_rn(acc[mt][nt][2], acc[mt][nt][3]);
        }
}

// ---------------- persistent recurrence (exact R6 shape + 2 zero-cost deltas) ----------------
// 128 CTAs = 2 dirs x 64 blocks of 32 gate rows (4 gates x 8 hidden units).
// Warps: mt = w>>2 (m16 tile of 2), nq = w&3 (batch quarter, n16).
static constexpr int HS_STRIDE = 520;   // halves
static constexpr int XS_STRIDE = 72;    // halves
static constexpr int ZS_STRIDE = 68;    // floats
static constexpr int SO_H  = 0;                        // 64 x 520 x 2 = 66560
static constexpr int SO_XW = 66560;                    // 32 x 72 x 2  = 4608
static constexpr int SO_Z  = 71168;                    // 32 x 68 x 4  = 8704
static constexpr int SO_B  = 79872;                    // 32 x 4
static constexpr int SMEM_SZ = 80000;

__global__ void __launch_bounds__(256, 1) recur_kernel(float* __restrict__ out) {
    extern __shared__ char smem[];
    __half* hs = (__half*)(smem + SO_H);
    __half* xs = (__half*)(smem + SO_XW);
    float*  zs = (float*)(smem + SO_Z);
    float*  bsm = (float*)(smem + SO_B);

    int cta = blockIdx.x;
    int dir = cta >> 6, rblk = cta & 63;
    int rbase = rblk * 32;
    int tid = threadIdx.x, w = tid >> 5, lane = tid & 31;
    int mt = w >> 2, nq = w & 3;
    uint32_t hs_base = (uint32_t)__cvta_generic_to_shared(hs);
    unsigned* bar = &g_bar[dir * 64];

    // ---- stage U (32 rows x 512), ldsm A-fragments into registers ----
#pragma unroll
    for (int p = 0; p < 8; p++) {
        int idx = tid + p * 256;
        int row = idx >> 6, c = idx & 63;
        *(uint4*)&hs[row * HS_STRIDE + c * 8] =
            *(const uint4*)&g_APERM[2 + dir][rbase + row][c * 8];
    }
    if (tid < 32) bsm[tid] = g_BIAS[dir][rbase + tid];
    __syncthreads();

    uint32_t a[32][4];
#pragma unroll
    for (int kk = 0; kk < 32; kk++) {
        int rr = mt * 16 + (lane & 15);
        int cc = kk * 16 + ((lane >> 4) & 1) * 8;
        ldsm_x4(a[kk][0], a[kk][1], a[kk][2], a[kk][3],
                hs_base + (uint32_t)(rr * HS_STRIDE + cc) * 2);
    }
    __syncthreads();

    float creg[2] = {0.f, 0.f};
    int eb = tid & 63;          // batch
    int hq = tid >> 6;          // hidden pair index (0..3), jp = hq*2 + q
    int xw_row = tid >> 3, xw_c = tid & 7;

    // prefetch XW for t = 0
    int sx0 = dir ? (SEQ - 1) : 0;
    uint4 xwr = *(const uint4*)&g_XW[dir][rbase + xw_row][sx0 * 64 + xw_c * 8];

    for (int t = 0; t < SEQ; t++) {
        int par = t & 1;
        int sx = dir ? (SEQ - 1 - t) : t;
        const __half* hsrc = &g_H[par][dir][0];

        // STS prefetched XW tile (loaded during previous barrier spin)
        *(uint4*)&xs[xw_row * XS_STRIDE + xw_c * 8] = xwr;

        // h: 64 batch rows x 512 halves, L1-bypass, LDG->STS (R6 path)
#pragma unroll
        for (int p = 0; p < 16; p++) {
            int idx = tid + p * 256;        // 4096 uint4
            int row = idx >> 6, c = idx & 63;
            *(uint4*)&hs[row * HS_STRIDE + c * 8] = ldg_cg(&hsrc[row * HID + c * 8]);
        }
        __syncthreads();

        float acc[2][4];
#pragma unroll
        for (int i = 0; i < 2; i++)
#pragma unroll
            for (int c = 0; c < 4; c++) acc[i][c] = 0.0f;

#pragma unroll
        for (int kk = 0; kk < 32; kk++) {
            uint32_t b0, b1, b2, b3;
            int rr = nq * 16 + ((lane >> 4) << 3) + (lane & 7);
            int cc = kk * 16 + ((lane >> 3) & 1) * 8;
            ldsm_x4(b0, b1, b2, b3, hs_base + (uint32_t)(rr * HS_STRIDE + cc) * 2);
            mma16816(acc[0], a[kk][0], a[kk][1], a[kk][2], a[kk][3], b0, b1);
            mma16816(acc[1], a[kk][0], a[kk][1], a[kk][2], a[kk][3], b2, b3);
        }
        // z -> SMEM exchange
#pragma unroll
        for (int i = 0; i < 2; i++) {
            int row = mt * 16 + (lane >> 2);
            int col = nq * 16 + i * 8 + (lane & 3) * 2;
            *(float2*)&zs[row * ZS_STRIDE + col]       = make_float2(acc[i][0], acc[i][1]);
            *(float2*)&zs[(row + 8) * ZS_STRIDE + col] = make_float2(acc[i][2], acc[i][3]);
        }
        __syncthreads();

        // cell update: thread owns (batch eb, hidden units hq*2, hq*2+1)
        float hv[2];
#pragma unroll
        for (int q = 0; q < 2; q++) {
            int jp = hq * 2 + q;
            float z0 = zs[jp * ZS_STRIDE + eb]        + __half2float(xs[jp * XS_STRIDE + eb])        + bsm[jp];
            float z1 = zs[(8 + jp) * ZS_STRIDE + eb]  + __half2float(xs[(8 + jp) * XS_STRIDE + eb])  + bsm[8 + jp];
            float z2 = zs[(16 + jp) * ZS_STRIDE + eb] + __half2float(xs[(16 + jp) * XS_STRIDE + eb]) + bsm[16 + jp];
            float z3 = zs[(24 + jp) * ZS_STRIDE + eb] + __half2float(xs[(24 + jp) * XS_STRIDE + eb]) + bsm[24 + jp];
            float ig = sigf(z0), fg = sigf(z1), gg = tanhf(z2), og = sigf(z3);
            creg[q] = fg * creg[q] + ig * gg;
            hv[q] = og * tanhf(creg[q]);
        }
        stg_cg32(&g_H[par ^ 1][dir][eb * HID + rblk * 8 + hq * 2], pack_h2(hv[0], hv[1]));
        *(float2*)&out[((size_t)eb * SEQ + sx) * 1024 + dir * 512 + rblk * 8 + hq * 2] =
            make_float2(hv[0], hv[1]);

        // per-direction grid barrier (64 CTAs); XW[t+1] prefetch hides in the spin
        __syncthreads();
        if (tid == 0) {
            asm volatile("red.release.gpu.global.add.u32 [%0], %1;" :: "l"(bar), "r"(1u) : "memory");
        }
        if (t + 1 < SEQ) {
            int sxn = dir ? (SEQ - 2 - t) : (t + 1);
            xwr = *(const uint4*)&g_XW[dir][rbase + xw_row][sxn * 64 + xw_c * 8];
        }
        if (tid == 0) {
            unsigned tgt = 64u * (unsigned)(t + 1), v;
            do {
                asm volatile("ld.acquire.gpu.global.u32 %0, [%1];" : "=r"(v) : "l"(bar));
            } while (v < tgt);
        }
        __syncthreads();
    }
}

// ---------------- launch ----------------
extern "C" void kernel_launch(void* const* d_in, const int* in_sizes, int n_in,
                              void* d_out, int out_size) {
    const int*   tokens = (const int*)d_in[0];
    const float* emb    = (const float*)d_in[1];
    const float* Wf     = (const float*)d_in[2];
    const float* Uf     = (const float*)d_in[3];
    const float* bf     = (const float*)d_in[4];
    const float* Wb     = (const float*)d_in[5];
    const float* Ub     = (const float*)d_in[6];
    const float* bb     = (const float*)d_in[7];
    float* out = (float*)d_out;

    cudaFuncSetAttribute(recur_kernel, cudaFuncAttributeMaxDynamicSharedMemorySize, SMEM_SZ);
    cudaFuncSetAttribute(xw_gemm_kernel, cudaFuncAttributeMaxDynamicSharedMemorySize, XW_SMEM);

    init_kernel<<<128, 256>>>();
    prep_w_kernel<<<256, 256>>>(Wf, Uf, bf, Wb, Ub, bb);
    gather_x_kernel<<<NTOK, 128>>>(tokens, emb);
    dim3 gg(256, 16, 2);
    xw_gemm_kernel<<<gg, 256, XW_SMEM>>>();
    recur_kernel<<<128, 256, SMEM_SZ>>>(out);
}

// round 11
// speedup vs baseline: 1.6764x; 1.1462x over previous
#include <cuda_runtime.h>
#include <cuda_fp16.h>
#include <cstdint>
#include <cstddef>

#define DINL __device__ __forceinline__

static constexpr int BATCH = 64;
static constexpr int SEQ   = 512;
static constexpr int EMB   = 512;
static constexpr int HID   = 512;
static constexpr int G4    = 2048;
static constexpr int NTOK  = BATCH * SEQ;

// Permuted fp16 weights: 0=Wf,1=Wb,2=Uf,3=Ub.
// Row r: rblk=r>>5, lr=r&31, g=lr>>3, jp=lr&7  <->  original column g*512 + rblk*8 + jp
__device__ __align__(16) __half g_APERM[4][G4][EMB];
__device__ __align__(16) __half g_X[(size_t)NTOK * EMB];
__device__ __align__(16) __half g_XW[2][G4][NTOK];
__device__ __align__(16) __half g_H[2][2][BATCH * HID];
__device__ float g_BIAS[2][G4];
__device__ unsigned g_bar[128];   // per-dir counters at [0] and [64]

// ---------------- helpers ----------------
DINL void ldsm_x4(uint32_t& r0, uint32_t& r1, uint32_t& r2, uint32_t& r3, uint32_t addr) {
    asm volatile("ldmatrix.sync.aligned.m8n8.x4.shared.b16 {%0,%1,%2,%3}, [%4];"
                 : "=r"(r0), "=r"(r1), "=r"(r2), "=r"(r3) : "r"(addr));
}
DINL void mma16816(float* d, uint32_t a0, uint32_t a1, uint32_t a2, uint32_t a3,
                   uint32_t b0, uint32_t b1) {
    asm volatile("mma.sync.aligned.m16n8k16.row.col.f32.f16.f16.f32 "
                 "{%0,%1,%2,%3}, {%4,%5,%6,%7}, {%8,%9}, {%0,%1,%2,%3};"
                 : "+f"(d[0]), "+f"(d[1]), "+f"(d[2]), "+f"(d[3])
                 : "r"(a0), "r"(a1), "r"(a2), "r"(a3), "r"(b0), "r"(b1));
}
DINL float sigf(float x) { return 1.0f / (1.0f + __expf(-x)); }
DINL uint4 ldg_cg(const void* p) {
    uint4 v;
    asm volatile("ld.global.cg.v4.u32 {%0,%1,%2,%3}, [%4];"
                 : "=r"(v.x), "=r"(v.y), "=r"(v.z), "=r"(v.w) : "l"(p));
    return v;
}
DINL void stg_cg16(void* p, uint16_t v) {
    asm volatile("st.global.cg.u16 [%0], %1;" :: "l"(p), "h"(v) : "memory");
}
DINL void cp16(uint32_t dst, const void* src) {
    asm volatile("cp.async.cg.shared.global [%0], [%1], 16;" :: "r"(dst), "l"(src) : "memory");
}
#define CP_COMMIT() asm volatile("cp.async.commit_group;" ::: "memory")
#define CP_WAIT(N)  asm volatile("cp.async.wait_group %0;" :: "n"(N) : "memory")

// ---------------- phase kernels ----------------
__global__ void init_kernel() {
    unsigned idx = blockIdx.x * blockDim.x + threadIdx.x;
    reinterpret_cast<uint32_t*>(g_H)[idx] = 0u;   // zero parity-0 h, both dirs
    if (idx < 128) g_bar[idx] = 0u;
}

// Coalesced transpose into permuted layout.
__global__ void __launch_bounds__(256) prep_w_kernel(
        const float* __restrict__ Wf, const float* __restrict__ Uf,
        const float* __restrict__ bf, const float* __restrict__ Wb,
        const float* __restrict__ Ub, const float* __restrict__ bb) {
    __shared__ __half tile[32][520];
    int m = blockIdx.x >> 6;
    int blk = blockIdx.x & 63;          // rblk = r>>5
    int rbase = blk * 32;
    int tid = threadIdx.x;
    int lr = tid & 31, eo = tid >> 5;
    int g = lr >> 3, jp = lr & 7;
    int col = g * 512 + blk * 8 + jp;
    const float* src = (m == 0) ? Wf : (m == 1) ? Wb : (m == 2) ? Uf : Ub;
#pragma unroll 8
    for (int es = 0; es < 64; es++) {
        int e = es * 8 + eo;
        tile[lr][e] = __float2half(src[(size_t)e * G4 + col]);
    }
    if (m < 2 && tid < 32) g_BIAS[m][rbase + lr] = (m ? bb : bf)[col];
    __syncthreads();
    int row = tid >> 3, c = tid & 7;
#pragma unroll
    for (int q = 0; q < 8; q++)
        *(uint4*)&g_APERM[m][rbase + row][(c + q * 8) * 8] =
            *(uint4*)&tile[row][(c + q * 8) * 8];
}

__global__ void gather_x_kernel(const int* __restrict__ tokens, const float* __restrict__ emb) {
    int i = blockIdx.x;
    int s = i >> 6, b = i & 63;
    int tok = tokens[b * SEQ + s];
    float4 v = reinterpret_cast<const float4*>(emb + (size_t)tok * EMB)[threadIdx.x];
    __half2* dst = reinterpret_cast<__half2*>(g_X + (size_t)i * EMB);
    dst[threadIdx.x * 2]     = __floats2half2_rn(v.x, v.y);
    dst[threadIdx.x * 2 + 1] = __floats2half2_rn(v.z, v.w);
}

// ---------------- xW GEMM (HMMA + cp.async double buffer; unchanged) ----------------
static constexpr int XBUF = 10240;
static constexpr int XW_SMEM = 4 * XBUF;

__global__ void __launch_bounds__(256) xw_gemm_kernel() {
    extern __shared__ char smx[];
    uint32_t sa = (uint32_t)__cvta_generic_to_shared(smx);
    uint32_t sbv = sa + 2 * XBUF;
    int dir = blockIdx.z, rbase = blockIdx.y * 128, ibase = blockIdx.x * 128;
    int tid = threadIdx.x, w = tid >> 5, lane = tid & 31;
    int wm = w & 3, wn = w >> 2;
    float acc[2][8][4];
#pragma unroll
    for (int a = 0; a < 2; a++)
#pragma unroll
        for (int b = 0; b < 8; b++)
#pragma unroll
            for (int c = 0; c < 4; c++) acc[a][b][c] = 0.0f;
    const __half* gA = &g_APERM[dir][0][0];

    auto load_chunk = [&](int kc, int buf) {
#pragma unroll
        for (int p = 0; p < 2; p++) {
            int ch = tid + p * 256, row = ch >> 2, c = ch & 3;
            cp16(sa  + buf * XBUF + (uint32_t)(row * 40 + c * 8) * 2,
                 &gA[(size_t)(rbase + row) * EMB + kc * 32 + c * 8]);
            cp16(sbv + buf * XBUF + (uint32_t)(row * 40 + c * 8) * 2,
                 &g_X[(size_t)(ibase + row) * EMB + kc * 32 + c * 8]);
        }
        CP_COMMIT();
    };

    load_chunk(0, 0);
    for (int kc = 0; kc < 16; kc++) {
        int cur = kc & 1;
        if (kc < 15) { load_chunk(kc + 1, cur ^ 1); CP_WAIT(1); }
        else         { CP_WAIT(0); }
        __syncthreads();
        uint32_t as_base = sa  + cur * XBUF;
        uint32_t bs_base = sbv + cur * XBUF;
#pragma unroll
        for (int kk = 0; kk < 2; kk++) {
            uint32_t a[2][4];
#pragma unroll
            for (int mt = 0; mt < 2; mt++) {
                int rr = wm * 32 + mt * 16 + (lane & 15);
                int cc = kk * 16 + ((lane >> 4) & 1) * 8;
                ldsm_x4(a[mt][0], a[mt][1], a[mt][2], a[mt][3],
                        as_base + (uint32_t)(rr * 40 + cc) * 2);
            }
            uint32_t bq[8][2];
#pragma unroll
            for (int bp = 0; bp < 4; bp++) {
                int rr = wn * 64 + bp * 16 + ((lane >> 4) << 3) + (lane & 7);
                int cc = kk * 16 + ((lane >> 3) & 1) * 8;
                ldsm_x4(bq[bp * 2][0], bq[bp * 2][1], bq[bp * 2 + 1][0], bq[bp * 2 + 1][1],
                        bs_base + (uint32_t)(rr * 40 + cc) * 2);
            }
#pragma unroll
            for (int mt = 0; mt < 2; mt++)
#pragma unroll
                for (int nt = 0; nt < 8; nt++)
                    mma16816(acc[mt][nt], a[mt][0], a[mt][1], a[mt][2], a[mt][3],
                             bq[nt][0], bq[nt][1]);
        }
        __syncthreads();
    }
    __half* gxw = &g_XW[dir][0][0];
#pragma unroll
    for (int mt = 0; mt < 2; mt++)
#pragma unroll
        for (int nt = 0; nt < 8; nt++) {
            size_t row = rbase + wm * 32 + mt * 16 + (lane >> 2);
            int col = ibase + wn * 64 + nt * 8 + (lane & 3) * 2;
            *(__half2*)&gxw[row * NTOK + col]       = __floats2half2_rn(acc[mt][nt][0], acc[mt][nt][1]);
            *(__half2*)&gxw[(row + 8) * NTOK + col] = __floats2half2_rn(acc[mt][nt][2], acc[mt][nt][3]);
        }
}

// ---------------- persistent recurrence: split-K, 512 threads, 16 warps ----------------
// 128 CTAs = 2 dirs x 64 blocks of 32 gate rows (4 gates x 8 hidden units).
// Warps: kh = w>>3 (K-half), mt = (w>>2)&1 (m16 tile), nq = w&3 (batch quarter n16).
static constexpr int HS_STRIDE = 520;   // halves
static constexpr int XS_STRIDE = 72;    // halves
static constexpr int ZS_STRIDE = 68;    // floats
static constexpr int SO_H  = 0;                        // 64 x 520 x 2 = 66560
static constexpr int SO_XW = 66560;                    // 32 x 72 x 2  = 4608
static constexpr int SO_Z  = 71168;                    // 2 x 32 x 68 x 4 = 17408
static constexpr int SO_B  = 88576;                    // 32 x 4
static constexpr int SMEM_SZ = 88704;

__global__ void __launch_bounds__(512, 1) recur_kernel(float* __restrict__ out) {
    extern __shared__ char smem[];
    __half* hs = (__half*)(smem + SO_H);
    __half* xs = (__half*)(smem + SO_XW);
    float*  zs = (float*)(smem + SO_Z);      // two partial buffers of 32 x ZS_STRIDE
    float*  bsm = (float*)(smem + SO_B);

    int cta = blockIdx.x;
    int dir = cta >> 6, rblk = cta & 63;
    int rbase = rblk * 32;
    int tid = threadIdx.x, w = tid >> 5, lane = tid & 31;
    int kh = w >> 3, mt = (w >> 2) & 1, nq = w & 3;
    uint32_t hs_base = (uint32_t)__cvta_generic_to_shared(hs);
    unsigned* bar = &g_bar[dir * 64];

    // ---- stage U (32 rows x 512), ldsm this warp's K-half A-fragments ----
#pragma unroll
    for (int p = 0; p < 4; p++) {
        int idx = tid + p * 512;            // 2048 uint4
        int row = idx >> 6, c = idx & 63;
        *(uint4*)&hs[row * HS_STRIDE + c * 8] =
            *(const uint4*)&g_APERM[2 + dir][rbase + row][c * 8];
    }
    if (tid < 32) bsm[tid] = g_BIAS[dir][rbase + tid];
    __syncthreads();

    uint32_t a[16][4];
#pragma unroll
    for (int kki = 0; kki < 16; kki++) {
        int kk = kh * 16 + kki;
        int rr = mt * 16 + (lane & 15);
        int cc = kk * 16 + ((lane >> 4) & 1) * 8;
        ldsm_x4(a[kki][0], a[kki][1], a[kki][2], a[kki][3],
                hs_base + (uint32_t)(rr * HS_STRIDE + cc) * 2);
    }
    __syncthreads();

    float creg = 0.0f;
    int eb = tid >> 3;          // batch (consecutive groups of 8 threads)
    int jp = tid & 7;           // hidden unit within 8-block
    int xw_row = tid >> 3, xw_c = tid & 7;   // only tid<256 loads XW

    // prefetch XW for t = 0
    int sx0 = dir ? (SEQ - 1) : 0;
    uint4 xwr = make_uint4(0, 0, 0, 0);
    if (tid < 256)
        xwr = *(const uint4*)&g_XW[dir][rbase + xw_row][sx0 * 64 + xw_c * 8];

    for (int t = 0; t < SEQ; t++) {
        int par = t & 1;
        int sx = dir ? (SEQ - 1 - t) : t;
        const __half* hsrc = &g_H[par][dir][0];

        // STS prefetched XW tile (tid<256)
        if (tid < 256)
            *(uint4*)&xs[xw_row * XS_STRIDE + xw_c * 8] = xwr;

        // h: 64 batch rows x 512 halves, L1-bypass, LDG->STS (8 per thread)
#pragma unroll
        for (int p = 0; p < 8; p++) {
            int idx = tid + p * 512;        // 4096 uint4
            int row = idx >> 6, c = idx & 63;
            *(uint4*)&hs[row * HS_STRIDE + c * 8] = ldg_cg(&hsrc[row * HID + c * 8]);
        }
        __syncthreads();

        float acc[2][4];
#pragma unroll
        for (int i = 0; i < 2; i++)
#pragma unroll
            for (int c = 0; c < 4; c++) acc[i][c] = 0.0f;

#pragma unroll
        for (int kki = 0; kki < 16; kki++) {
            int kk = kh * 16 + kki;
            uint32_t b0, b1, b2, b3;
            int rr = nq * 16 + ((lane >> 4) << 3) + (lane & 7);
            int cc = kk * 16 + ((lane >> 3) & 1) * 8;
            ldsm_x4(b0, b1, b2, b3, hs_base + (uint32_t)(rr * HS_STRIDE + cc) * 2);
            mma16816(acc[0], a[kki][0], a[kki][1], a[kki][2], a[kki][3], b0, b1);
            mma16816(acc[1], a[kki][0], a[kki][1], a[kki][2], a[kki][3], b2, b3);
        }
        // partial z -> SMEM (buffer kh)
        float* zsp = zs + kh * 32 * ZS_STRIDE;
#pragma unroll
        for (int i = 0; i < 2; i++) {
            int row = mt * 16 + (lane >> 2);
            int col = nq * 16 + i * 8 + (lane & 3) * 2;
            *(float2*)&zsp[row * ZS_STRIDE + col]       = make_float2(acc[i][0], acc[i][1]);
            *(float2*)&zsp[(row + 8) * ZS_STRIDE + col] = make_float2(acc[i][2], acc[i][3]);
        }
        __syncthreads();

        // cell update: thread owns (batch eb, hidden unit jp)
        float* zs0 = zs;
        float* zs1 = zs + 32 * ZS_STRIDE;
        float z0 = zs0[jp * ZS_STRIDE + eb]        + zs1[jp * ZS_STRIDE + eb]
                 + __half2float(xs[jp * XS_STRIDE + eb])        + bsm[jp];
        float z1 = zs0[(8 + jp) * ZS_STRIDE + eb]  + zs1[(8 + jp) * ZS_STRIDE + eb]
                 + __half2float(xs[(8 + jp) * XS_STRIDE + eb])  + bsm[8 + jp];
        float z2 = zs0[(16 + jp) * ZS_STRIDE + eb] + zs1[(16 + jp) * ZS_STRIDE + eb]
                 + __half2float(xs[(16 + jp) * XS_STRIDE + eb]) + bsm[16 + jp];
        float z3 = zs0[(24 + jp) * ZS_STRIDE + eb] + zs1[(24 + jp) * ZS_STRIDE + eb]
                 + __half2float(xs[(24 + jp) * XS_STRIDE + eb]) + bsm[24 + jp];
        float ig = sigf(z0), fg = sigf(z1), gg = tanhf(z2), og = sigf(z3);
        creg = fg * creg + ig * gg;
        float hv = og * tanhf(creg);

        // h store (must precede the barrier arrive)
        stg_cg16(&g_H[par ^ 1][dir][eb * HID + rblk * 8 + jp],
                 (uint16_t)__half_as_ushort(__float2half_rn(hv)));

        __syncthreads();
        if (tid == 0) {
            asm volatile("red.release.gpu.global.add.u32 [%0], %1;" :: "l"(bar), "r"(1u) : "memory");
        }
        // off-critical-path work rides the spin: out store + XW[t+1] prefetch
        out[((size_t)eb * SEQ + sx) * 1024 + dir * 512 + rblk * 8 + jp] = hv;
        if (t + 1 < SEQ && tid < 256) {
            int sxn = dir ? (SEQ - 2 - t) : (t + 1);
            xwr = *(const uint4*)&g_XW[dir][rbase + xw_row][sxn * 64 + xw_c * 8];
        }
        if (tid == 0) {
            unsigned tgt = 64u * (unsigned)(t + 1), v;
            do {
                asm volatile("ld.acquire.gpu.global.u32 %0, [%1];" : "=r"(v) : "l"(bar));
            } while (v < tgt);
        }
        __syncthreads();
    }
}

// ---------------- launch ----------------
extern "C" void kernel_launch(void* const* d_in, const int* in_sizes, int n_in,
                              void* d_out, int out_size) {
    const int*   tokens = (const int*)d_in[0];
    const float* emb    = (const float*)d_in[1];
    const float* Wf     = (const float*)d_in[2];
    const float* Uf     = (const float*)d_in[3];
    const float* bf     = (const float*)d_in[4];
    const float* Wb     = (const float*)d_in[5];
    const float* Ub     = (const float*)d_in[6];
    const float* bb     = (const float*)d_in[7];
    float* out = (float*)d_out;

    cudaFuncSetAttribute(recur_kernel, cudaFuncAttributeMaxDynamicSharedMemorySize, SMEM_SZ);
    cudaFuncSetAttribute(xw_gemm_kernel, cudaFuncAttributeMaxDynamicSharedMemorySize, XW_SMEM);

    init_kernel<<<128, 256>>>();
    prep_w_kernel<<<256, 256>>>(Wf, Uf, bf, Wb, Ub, bb);
    gather_x_kernel<<<NTOK, 128>>>(tokens, emb);
    dim3 gg(256, 16, 2);
    xw_gemm_kernel<<<gg, 256, XW_SMEM>>>();
    recur_kernel<<<128, 512, SMEM_SZ>>>(out);
}

// round 13
// speedup vs baseline: 1.9597x; 1.1690x over previous
#include <cuda_runtime.h>
#include <cuda_fp16.h>
#include <cstdint>
#include <cstddef>

#define DINL __device__ __forceinline__

static constexpr int BATCH = 64;
static constexpr int SEQ   = 512;
static constexpr int EMB   = 512;
static constexpr int HID   = 512;
static constexpr int G4    = 2048;
static constexpr int NTOK  = BATCH * SEQ;

// Permuted fp16 weights: 0=Wf,1=Wb,2=Uf,3=Ub.
// Row r: m=r>>7, g=(r>>5)&3, jp=r&31  <->  original column g*512 + m*32 + jp
__device__ __align__(16) __half g_APERM[4][G4][EMB];
__device__ __align__(16) __half g_X[(size_t)NTOK * EMB];
__device__ __align__(16) __half g_XW[2][G4][NTOK];
__device__ __align__(16) __half g_H[2][2][BATCH * HID];
__device__ float g_BIAS[2][G4];
__device__ unsigned g_bar[256];   // 8 group counters at gid*32

// ---------------- helpers ----------------
DINL void ldsm_x4(uint32_t& r0, uint32_t& r1, uint32_t& r2, uint32_t& r3, uint32_t addr) {
    asm volatile("ldmatrix.sync.aligned.m8n8.x4.shared.b16 {%0,%1,%2,%3}, [%4];"
                 : "=r"(r0), "=r"(r1), "=r"(r2), "=r"(r3) : "r"(addr));
}
DINL void mma16816(float* d, uint32_t a0, uint32_t a1, uint32_t a2, uint32_t a3,
                   uint32_t b0, uint32_t b1) {
    asm volatile("mma.sync.aligned.m16n8k16.row.col.f32.f16.f16.f32 "
                 "{%0,%1,%2,%3}, {%4,%5,%6,%7}, {%8,%9}, {%0,%1,%2,%3};"
                 : "+f"(d[0]), "+f"(d[1]), "+f"(d[2]), "+f"(d[3])
                 : "r"(a0), "r"(a1), "r"(a2), "r"(a3), "r"(b0), "r"(b1));
}
DINL float sigf(float x) { return 1.0f / (1.0f + __expf(-x)); }
DINL uint4 ldg_cg(const void* p) {
    uint4 v;
    asm volatile("ld.global.cg.v4.u32 {%0,%1,%2,%3}, [%4];"
                 : "=r"(v.x), "=r"(v.y), "=r"(v.z), "=r"(v.w) : "l"(p));
    return v;
}
DINL void stg_cg16(void* p, uint16_t v) {
    asm volatile("st.global.cg.u16 [%0], %1;" :: "l"(p), "h"(v) : "memory");
}
DINL void cp16(uint32_t dst, const void* src) {
    asm volatile("cp.async.cg.shared.global [%0], [%1], 16;" :: "r"(dst), "l"(src) : "memory");
}
#define CP_COMMIT() asm volatile("cp.async.commit_group;" ::: "memory")
#define CP_WAIT(N)  asm volatile("cp.async.wait_group %0;" :: "n"(N) : "memory")

// ---------------- phase kernels ----------------
__global__ void init_kernel() {
    unsigned idx = blockIdx.x * blockDim.x + threadIdx.x;
    reinterpret_cast<uint32_t*>(g_H)[idx] = 0u;   // zero parity-0 h, both dirs
    if (idx < 256) g_bar[idx] = 0u;
}

// Coalesced transpose into permuted layout.
// 32-row block blk: m=blk>>2, g=blk&3 -> colbase = g*512 + m*32, col = colbase + lr.
__global__ void __launch_bounds__(256) prep_w_kernel(
        const float* __restrict__ Wf, const float* __restrict__ Uf,
        const float* __restrict__ bf, const float* __restrict__ Wb,
        const float* __restrict__ Ub, const float* __restrict__ bb) {
    __shared__ __half tile[32][520];
    int mat = blockIdx.x >> 6;
    int blk = blockIdx.x & 63;
    int rbase = blk * 32;
    int tid = threadIdx.x;
    int lr = tid & 31, eo = tid >> 5;
    int colbase = (blk & 3) * 512 + (blk >> 2) * 32;
    int col = colbase + lr;
    const float* src = (mat == 0) ? Wf : (mat == 1) ? Wb : (mat == 2) ? Uf : Ub;
#pragma unroll 8
    for (int es = 0; es < 64; es++) {
        int e = es * 8 + eo;
        tile[lr][e] = __float2half(src[(size_t)e * G4 + col]);
    }
    if (mat < 2 && tid < 32) g_BIAS[mat][rbase + lr] = (mat ? bb : bf)[col];
    __syncthreads();
    int row = tid >> 3, c = tid & 7;
#pragma unroll
    for (int q = 0; q < 8; q++)
        *(uint4*)&g_APERM[mat][rbase + row][(c + q * 8) * 8] =
            *(uint4*)&tile[row][(c + q * 8) * 8];
}

__global__ void gather_x_kernel(const int* __restrict__ tokens, const float* __restrict__ emb) {
    int i = blockIdx.x;
    int s = i >> 6, b = i & 63;
    int tok = tokens[b * SEQ + s];
    float4 v = reinterpret_cast<const float4*>(emb + (size_t)tok * EMB)[threadIdx.x];
    __half2* dst = reinterpret_cast<__half2*>(g_X + (size_t)i * EMB);
    dst[threadIdx.x * 2]     = __floats2half2_rn(v.x, v.y);
    dst[threadIdx.x * 2 + 1] = __floats2half2_rn(v.z, v.w);
}

// ---------------- xW GEMM (HMMA + cp.async double buffer; unchanged) ----------------
static constexpr int XBUF = 10240;
static constexpr int XW_SMEM = 4 * XBUF;

__global__ void __launch_bounds__(256) xw_gemm_kernel() {
    extern __shared__ char smx[];
    uint32_t sa = (uint32_t)__cvta_generic_to_shared(smx);
    uint32_t sbv = sa + 2 * XBUF;
    int dir = blockIdx.z, rbase = blockIdx.y * 128, ibase = blockIdx.x * 128;
    int tid = threadIdx.x, w = tid >> 5, lane = tid & 31;
    int wm = w & 3, wn = w >> 2;
    float acc[2][8][4];
#pragma unroll
    for (int a = 0; a < 2; a++)
#pragma unroll
        for (int b = 0; b < 8; b++)
#pragma unroll
            for (int c = 0; c < 4; c++) acc[a][b][c] = 0.0f;
    const __half* gA = &g_APERM[dir][0][0];

    auto load_chunk = [&](int kc, int buf) {
#pragma unroll
        for (int p = 0; p < 2; p++) {
            int ch = tid + p * 256, row = ch >> 2, c = ch & 3;
            cp16(sa  + buf * XBUF + (uint32_t)(row * 40 + c * 8) * 2,
                 &gA[(size_t)(rbase + row) * EMB + kc * 32 + c * 8]);
            cp16(sbv + buf * XBUF + (uint32_t)(row * 40 + c * 8) * 2,
                 &g_X[(size_t)(ibase + row) * EMB + kc * 32 + c * 8]);
        }
        CP_COMMIT();
    };

    load_chunk(0, 0);
    for (int kc = 0; kc < 16; kc++) {
        int cur = kc & 1;
        if (kc < 15) { load_chunk(kc + 1, cur ^ 1); CP_WAIT(1); }
        else         { CP_WAIT(0); }
        __syncthreads();
        uint32_t as_base = sa  + cur * XBUF;
        uint32_t bs_base = sbv + cur * XBUF;
#pragma unroll
        for (int kk = 0; kk < 2; kk++) {
            uint32_t a[2][4];
#pragma unroll
            for (int mt = 0; mt < 2; mt++) {
                int rr = wm * 32 + mt * 16 + (lane & 15);
                int cc = kk * 16 + ((lane >> 4) & 1) * 8;
                ldsm_x4(a[mt][0], a[mt][1], a[mt][2], a[mt][3],
                        as_base + (uint32_t)(rr * 40 + cc) * 2);
            }
            uint32_t bq[8][2];
#pragma unroll
            for (int bp = 0; bp < 4; bp++) {
                int rr = wn * 64 + bp * 16 + ((lane >> 4) << 3) + (lane & 7);
                int cc = kk * 16 + ((lane >> 3) & 1) * 8;
                ldsm_x4(bq[bp * 2][0], bq[bp * 2][1], bq[bp * 2 + 1][0], bq[bp * 2 + 1][1],
                        bs_base + (uint32_t)(rr * 40 + cc) * 2);
            }
#pragma unroll
            for (int mt = 0; mt < 2; mt++)
#pragma unroll
                for (int nt = 0; nt < 8; nt++)
                    mma16816(acc[mt][nt], a[mt][0], a[mt][1], a[mt][2], a[mt][3],
                             bq[nt][0], bq[nt][1]);
        }
        __syncthreads();
    }
    __half* gxw = &g_XW[dir][0][0];
#pragma unroll
    for (int mt = 0; mt < 2; mt++)
#pragma unroll
        for (int nt = 0; nt < 8; nt++) {
            size_t row = rbase + wm * 32 + mt * 16 + (lane >> 2);
            int col = ibase + wn * 64 + nt * 8 + (lane & 3) * 2;
            *(__half2*)&gxw[row * NTOK + col]       = __floats2half2_rn(acc[mt][nt][0], acc[mt][nt][1]);
            *(__half2*)&gxw[(row + 8) * NTOK + col] = __floats2half2_rn(acc[mt][nt][2], acc[mt][nt][3]);
        }
}

// ---------------- persistent recurrence: 2-D (gate x batch) partitioning ----------------
// 128 CTAs = 2 dirs x 4 batch-groups (16 batches) x 16 gate-blocks (128 rows = 4 gates x 32 units).
// 512 threads = 16 warps: mt = w>>1 (m16 tile 0..7), kh = w&1 (K-half).
static constexpr int HS_STRIDE = 520;   // halves, 16 batch rows
static constexpr int XS_STRIDE = 22;    // halves (odd word stride -> conflict-free epilogue)
static constexpr int ZS_STRIDE = 21;    // floats (odd -> conflict-free epilogue)
static constexpr int SO_H  = 0;                        // 16 x 520 x 2 = 16640
static constexpr int SO_XW = 16640;                    // 128 x 22 x 2 = 5632  -> 22272
static constexpr int SO_Z  = 22272;                    // 2 x 128 x 21 x 4 = 21504 -> 43776
static constexpr int SO_B  = 43776;                    // 128 x 4 = 512
static constexpr int SMEM_SZ = 44416;

__global__ void __launch_bounds__(512, 1) recur_kernel(float* __restrict__ out) {
    extern __shared__ char smem[];
    __half* hs = (__half*)(smem + SO_H);
    __half* xs = (__half*)(smem + SO_XW);
    float*  zs = (float*)(smem + SO_Z);      // two K-half partial buffers of 128 x ZS_STRIDE
    float*  bsm = (float*)(smem + SO_B);

    int cta = blockIdx.x;
    int dir = cta >> 6, bg = (cta >> 4) & 3, m = cta & 15;
    int rbase = m * 128;
    int tid = threadIdx.x, w = tid >> 5, lane = tid & 31;
    int mt = w >> 1, kh = w & 1;
    uint32_t hs_base = (uint32_t)__cvta_generic_to_shared(hs);
    unsigned* bar = &g_bar[(dir * 4 + bg) * 32];

    // ---- stage U (128 rows x 512) in 8 passes of 16 rows; ldsm A-fragments ----
    uint32_t a[16][4];
    for (int s = 0; s < 8; s++) {
#pragma unroll
        for (int p = 0; p < 2; p++) {
            int idx = tid + p * 512;            // 1024 uint4: 16 rows x 64
            int row = idx >> 6, c = idx & 63;
            *(uint4*)&hs[row * HS_STRIDE + c * 8] =
                *(const uint4*)&g_APERM[2 + dir][rbase + s * 16 + row][c * 8];
        }
        __syncthreads();
        if (mt == s) {
#pragma unroll
            for (int kki = 0; kki < 16; kki++) {
                int kk = kh * 16 + kki;
                int rr = lane & 15;
                int cc = kk * 16 + ((lane >> 4) & 1) * 8;
                ldsm_x4(a[kki][0], a[kki][1], a[kki][2], a[kki][3],
                        hs_base + (uint32_t)(rr * HS_STRIDE + cc) * 2);
            }
        }
        __syncthreads();
    }
    if (tid < 128) bsm[tid] = g_BIAS[dir][rbase + tid];

    float creg = 0.0f;
    int eb = tid >> 5;          // local batch 0..15 (warp-uniform)
    int jp = tid & 31;          // hidden unit 0..31
    int xw_row = tid >> 3, xw_u = tid & 7;   // XW prefetch: rows xw_row & xw_row+64, u32 slot xw_u

    // prefetch XW for t = 0 (IDENTICAL slot mapping to the steady-state prefetch)
    int sx0 = dir ? (SEQ - 1) : 0;
    uint32_t xw0, xw1;
    xw0 = *(const uint32_t*)((const char*)&g_XW[dir][rbase + xw_row][sx0 * 64 + bg * 16] + xw_u * 4);
    xw1 = *(const uint32_t*)((const char*)&g_XW[dir][rbase + 64 + xw_row][sx0 * 64 + bg * 16] + xw_u * 4);

    for (int t = 0; t < SEQ; t++) {
        int par = t & 1;
        int sx = dir ? (SEQ - 1 - t) : t;
        const __half* hsrc = &g_H[par][dir][0];

        // STS prefetched XW tile: rows xw_row and xw_row+64, u32 slot xw_u
        *(uint32_t*)&xs[xw_row * XS_STRIDE + xw_u * 2] = xw0;
        *(uint32_t*)&xs[(xw_row + 64) * XS_STRIDE + xw_u * 2] = xw1;

        // h: 16 batch rows x 512 halves = 1024 uint4; 2 per thread
#pragma unroll
        for (int p = 0; p < 2; p++) {
            int idx = tid + p * 512;
            int row = idx >> 6, c = idx & 63;
            *(uint4*)&hs[row * HS_STRIDE + c * 8] =
                ldg_cg(&hsrc[(bg * 16 + row) * HID + c * 8]);
        }
        __syncthreads();

        float acc[2][4];
#pragma unroll
        for (int i = 0; i < 2; i++)
#pragma unroll
            for (int c = 0; c < 4; c++) acc[i][c] = 0.0f;

#pragma unroll
        for (int kki = 0; kki < 16; kki++) {
            int kk = kh * 16 + kki;
            uint32_t b0, b1, b2, b3;
            int rr = ((lane >> 4) << 3) + (lane & 7);   // batch rows 0..15
            int cc = kk * 16 + ((lane >> 3) & 1) * 8;
            ldsm_x4(b0, b1, b2, b3, hs_base + (uint32_t)(rr * HS_STRIDE + cc) * 2);
            mma16816(acc[0], a[kki][0], a[kki][1], a[kki][2], a[kki][3], b0, b1);
            mma16816(acc[1], a[kki][0], a[kki][1], a[kki][2], a[kki][3], b2, b3);
        }
        // partial z -> SMEM buffer kh: rows mt*16..+15, cols 0..15
        float* zsp = zs + kh * 128 * ZS_STRIDE;
#pragma unroll
        for (int i = 0; i < 2; i++) {
            int row = mt * 16 + (lane >> 2);
            int col = i * 8 + (lane & 3) * 2;
            zsp[row * ZS_STRIDE + col]           = acc[i][0];
            zsp[row * ZS_STRIDE + col + 1]       = acc[i][1];
            zsp[(row + 8) * ZS_STRIDE + col]     = acc[i][2];
            zsp[(row + 8) * ZS_STRIDE + col + 1] = acc[i][3];
        }
        __syncthreads();

        // cell update: thread owns (local batch eb, hidden unit jp)
        float* zs0 = zs;
        float* zs1 = zs + 128 * ZS_STRIDE;
        float z0 = zs0[jp * ZS_STRIDE + eb]         + zs1[jp * ZS_STRIDE + eb]
                 + __half2float(xs[jp * XS_STRIDE + eb])         + bsm[jp];
        float z1 = zs0[(32 + jp) * ZS_STRIDE + eb]  + zs1[(32 + jp) * ZS_STRIDE + eb]
                 + __half2float(xs[(32 + jp) * XS_STRIDE + eb])  + bsm[32 + jp];
        float z2 = zs0[(64 + jp) * ZS_STRIDE + eb]  + zs1[(64 + jp) * ZS_STRIDE + eb]
                 + __half2float(xs[(64 + jp) * XS_STRIDE + eb])  + bsm[64 + jp];
        float z3 = zs0[(96 + jp) * ZS_STRIDE + eb]  + zs1[(96 + jp) * ZS_STRIDE + eb]
                 + __half2float(xs[(96 + jp) * XS_STRIDE + eb])  + bsm[96 + jp];
        float ig = sigf(z0), fg = sigf(z1), gg = tanhf(z2), og = sigf(z3);
        creg = fg * creg + ig * gg;
        float hv = og * tanhf(creg);

        // h store (must precede the barrier arrive)
        stg_cg16(&g_H[par ^ 1][dir][(bg * 16 + eb) * HID + m * 32 + jp],
                 (uint16_t)__half_as_ushort(__float2half_rn(hv)));

        __syncthreads();
        if (tid == 0) {
            asm volatile("red.release.gpu.global.add.u32 [%0], %1;" :: "l"(bar), "r"(1u) : "memory");
        }
        // off-critical-path: out store + XW[t+1] prefetch ride the spin
        out[((size_t)(bg * 16 + eb) * SEQ + sx) * 1024 + dir * 512 + m * 32 + jp] = hv;
        if (t + 1 < SEQ) {
            int sxn = dir ? (SEQ - 2 - t) : (t + 1);
            xw0 = *(const uint32_t*)((const char*)&g_XW[dir][rbase + xw_row][sxn * 64 + bg * 16] + xw_u * 4);
            xw1 = *(const uint32_t*)((const char*)&g_XW[dir][rbase + 64 + xw_row][sxn * 64 + bg * 16] + xw_u * 4);
        }
        if (tid == 0) {
            unsigned tgt = 16u * (unsigned)(t + 1), v;
            do {
                asm volatile("ld.acquire.gpu.global.u32 %0, [%1];" : "=r"(v) : "l"(bar));
            } while (v < tgt);
        }
        __syncthreads();
    }
}

// ---------------- launch ----------------
extern "C" void kernel_launch(void* const* d_in, const int* in_sizes, int n_in,
                              void* d_out, int out_size) {
    const int*   tokens = (const int*)d_in[0];
    const float* emb    = (const float*)d_in[1];
    const float* Wf     = (const float*)d_in[2];
    const float* Uf     = (const float*)d_in[3];
    const float* bf     = (const float*)d_in[4];
    const float* Wb     = (const float*)d_in[5];
    const float* Ub     = (const float*)d_in[6];
    const float* bb     = (const float*)d_in[7];
    float* out = (float*)d_out;

    cudaFuncSetAttribute(recur_kernel, cudaFuncAttributeMaxDynamicSharedMemorySize, SMEM_SZ);
    cudaFuncSetAttribute(xw_gemm_kernel, cudaFuncAttributeMaxDynamicSharedMemorySize, XW_SMEM);

    init_kernel<<<128, 256>>>();
    prep_w_kernel<<<256, 256>>>(Wf, Uf, bf, Wb, Ub, bb);
    gather_x_kernel<<<NTOK, 128>>>(tokens, emb);
    dim3 gg(256, 16, 2);
    xw_gemm_kernel<<<gg, 256, XW_SMEM>>>();
    recur_kernel<<<128, 512, SMEM_SZ>>>(out);
}